// round 1
// baseline (speedup 1.0000x reference)
#include <cuda_runtime.h>

// ConvEnhanced: 2x2 valid conv + ReLU -> channel 0.
// "Quantum" 4-qubit circuit collapses analytically to
//   qval = cos(p00)*cos(p01)*cos(p11)
// (RZ layers are pure phases, CNOT layers are permutations; Z0 after two
// CNOT layers = Z0 Z1 Z3 on the product state). qparams are unused.
// Channel 1 = qval replicated over each 2x2 patch.
//
// x:      [64, 1, 257, 257] f32
// conv_w: [1, 1, 2, 2] f32
// conv_b: [1] f32
// qparams:[2, 4] f32 (provably irrelevant to the output)
// out:    [64, 2, 256, 256] f32

#define IN_HW   257
#define OUT_HW  256
#define HP      128            // patches per side
#define BATCH   64
#define N_PATCH (BATCH * HP * HP)   // 1,048,576

__global__ __launch_bounds__(256)
void conv_enhanced_kernel(const float* __restrict__ x,
                          const float* __restrict__ w,
                          const float* __restrict__ bias,
                          float* __restrict__ out)
{
    int idx = blockIdx.x * blockDim.x + threadIdx.x;   // exact grid, no guard needed
    int pw = idx & (HP - 1);
    int ph = (idx >> 7) & (HP - 1);
    int b  = idx >> 14;

    const float w00 = __ldg(w + 0);
    const float w01 = __ldg(w + 1);
    const float w10 = __ldg(w + 2);
    const float w11 = __ldg(w + 3);
    const float bb  = __ldg(bias);

    const int r = ph * 2;
    const int c = pw * 2;
    const float* row0 = x + (size_t)b * (IN_HW * IN_HW) + r * IN_HW + c;
    const float* row1 = row0 + IN_HW;
    const float* row2 = row1 + IN_HW;

    const float x00 = row0[0], x01 = row0[1], x02 = row0[2];
    const float x10 = row1[0], x11 = row1[1], x12 = row1[2];
    const float x20 = row2[0], x21 = row2[1], x22 = row2[2];

    const float p00 = fmaxf(fmaf(w00, x00, fmaf(w01, x01, fmaf(w10, x10, fmaf(w11, x11, bb)))), 0.f);
    const float p01 = fmaxf(fmaf(w00, x01, fmaf(w01, x02, fmaf(w10, x11, fmaf(w11, x12, bb)))), 0.f);
    const float p10 = fmaxf(fmaf(w00, x10, fmaf(w01, x11, fmaf(w10, x20, fmaf(w11, x21, bb)))), 0.f);
    const float p11 = fmaxf(fmaf(w00, x11, fmaf(w01, x12, fmaf(w10, x21, fmaf(w11, x22, bb)))), 0.f);

    const float q = cosf(p00) * cosf(p01) * cosf(p11);

    float* ob = out + (size_t)b * (2 * OUT_HW * OUT_HW);
    const int o0 = r * OUT_HW + c;                 // c even -> 8B aligned

    // channel 0: conv+relu
    *reinterpret_cast<float2*>(ob + o0)          = make_float2(p00, p01);
    *reinterpret_cast<float2*>(ob + o0 + OUT_HW) = make_float2(p10, p11);
    // channel 1: qmap (2x2 replicated)
    float* ob1 = ob + OUT_HW * OUT_HW;
    const float2 qq = make_float2(q, q);
    *reinterpret_cast<float2*>(ob1 + o0)          = qq;
    *reinterpret_cast<float2*>(ob1 + o0 + OUT_HW) = qq;
}

extern "C" void kernel_launch(void* const* d_in, const int* in_sizes, int n_in,
                              void* d_out, int out_size)
{
    const float* x      = (const float*)d_in[0];
    const float* conv_w = (const float*)d_in[1];
    const float* conv_b = (const float*)d_in[2];
    // d_in[3] = qparams: provably unused (phases only, measurement diagonal)
    float* out = (float*)d_out;

    const int threads = 256;
    const int blocks  = N_PATCH / threads;   // 4096
    conv_enhanced_kernel<<<blocks, threads>>>(x, conv_w, conv_b, out);
}

// round 2
// speedup vs baseline: 1.0030x; 1.0030x over previous
#include <cuda_runtime.h>

// ConvEnhanced: 2x2 valid conv + ReLU -> channel 0.
// Quantum circuit collapses analytically: RZ layers are diagonal phases,
// CNOT layers are permutations, measurement Z0 after two CNOT layers
// equals Z0*Z1*Z3 on the RX product state =>
//   qval = cos(p00)*cos(p01)*cos(p11)    (qparams irrelevant)
// Channel 1 = qval replicated over each 2x2 patch.
//
// x: [64,1,257,257] f32; out: [64,2,256,256] f32.
// Each thread computes TWO horizontal patches (4 output columns x 2 rows),
// enabling pure STG.128 stores. __cosf used (abs err ~1e-5 << 1e-3 thresh).

#define IN_HW   257
#define OUT_HW  256
#define HP      128
#define BATCH   64
// one thread per pair of horizontal patches:
#define N_THREADS (BATCH * HP * (HP / 2))   // 524,288

__global__ __launch_bounds__(256)
void conv_enhanced_kernel(const float* __restrict__ x,
                          const float* __restrict__ w,
                          const float* __restrict__ bias,
                          float* __restrict__ out)
{
    const int idx = blockIdx.x * blockDim.x + threadIdx.x;  // exact grid
    const int pp = idx & 63;            // patch-pair index within row (64 pairs)
    const int ph = (idx >> 6) & (HP - 1);
    const int b  = idx >> 13;

    const float w00 = __ldg(w + 0);
    const float w01 = __ldg(w + 1);
    const float w10 = __ldg(w + 2);
    const float w11 = __ldg(w + 3);
    const float bb  = __ldg(bias);

    const int r = ph * 2;
    const int c = pp * 4;               // input col start; needs cols c..c+4
    const float* row0 = x + (size_t)b * (IN_HW * IN_HW) + r * IN_HW + c;
    const float* row1 = row0 + IN_HW;
    const float* row2 = row1 + IN_HW;

    float x0[5], x1[5], x2[5];
#pragma unroll
    for (int j = 0; j < 5; ++j) { x0[j] = __ldg(row0 + j); }
#pragma unroll
    for (int j = 0; j < 5; ++j) { x1[j] = __ldg(row1 + j); }
#pragma unroll
    for (int j = 0; j < 5; ++j) { x2[j] = __ldg(row2 + j); }

    float p0[4], p1[4];
#pragma unroll
    for (int j = 0; j < 4; ++j) {
        p0[j] = fmaxf(fmaf(w00, x0[j], fmaf(w01, x0[j+1],
                        fmaf(w10, x1[j], fmaf(w11, x1[j+1], bb)))), 0.f);
        p1[j] = fmaxf(fmaf(w00, x1[j], fmaf(w01, x1[j+1],
                        fmaf(w10, x2[j], fmaf(w11, x2[j+1], bb)))), 0.f);
    }

    // qval per patch: cos(p00)*cos(p01)*cos(p11)
    const float qA = __cosf(p0[0]) * __cosf(p0[1]) * __cosf(p1[1]);
    const float qB = __cosf(p0[2]) * __cosf(p0[3]) * __cosf(p1[3]);

    float* ob = out + (size_t)b * (2 * OUT_HW * OUT_HW);
    const int o0 = r * OUT_HW + c;      // c multiple of 4 -> 16B aligned

    *reinterpret_cast<float4*>(ob + o0)          = make_float4(p0[0], p0[1], p0[2], p0[3]);
    *reinterpret_cast<float4*>(ob + o0 + OUT_HW) = make_float4(p1[0], p1[1], p1[2], p1[3]);

    float* ob1 = ob + OUT_HW * OUT_HW;
    const float4 qv = make_float4(qA, qA, qB, qB);
    *reinterpret_cast<float4*>(ob1 + o0)          = qv;
    *reinterpret_cast<float4*>(ob1 + o0 + OUT_HW) = qv;
}

extern "C" void kernel_launch(void* const* d_in, const int* in_sizes, int n_in,
                              void* d_out, int out_size)
{
    const float* x      = (const float*)d_in[0];
    const float* conv_w = (const float*)d_in[1];
    const float* conv_b = (const float*)d_in[2];
    // d_in[3] = qparams: provably unused
    float* out = (float*)d_out;

    const int threads = 256;
    const int blocks  = N_THREADS / threads;   // 2048
    conv_enhanced_kernel<<<blocks, threads>>>(x, conv_w, conv_b, out);
}